// round 13
// baseline (speedup 1.0000x reference)
#include <cuda_runtime.h>
#include <math.h>

// result = sum_{b,t} w^2 * log(sigmoid(logit)+EPS) * log_probs * (t+1) / sum(w)
// (reversed cumsum then total sum == (t+1)-weighted sum)
//
// R11 = R9 (grid-stride loop, fast MUFU chain, double-atomic epilogue,
// self-resetting counter) + in-loop unroll x2: 6 independent LDG.128 per
// trip, loop pipelining preserved. Hot kernel requires n4 % (2*stride) == 0
// (true here: n4 = 2^21, stride = 1024*256 = 2^18 -> 4 double-trips).

#define T_DIM    16384          // inner dim (power of 2)
#define NTHREADS 256
#define HOTBLOCKS 1024          // stride = 2^18 divides n4 = 2^21
#define GENBLOCKS (148 * 8)

__device__ double        g_acc_t;   // zero-init at load; reset by last block
__device__ double        g_acc_w;
__device__ unsigned int  g_count;   // wraps to 0 every pass (atomicInc)

__device__ __forceinline__ float term_elem(float lp, float lg, float w, float tscale) {
    // log(sigmoid(lg)+eps) ~= -log1p(exp(-lg)); eps shift < 1e-5 relative here
    float e = __expf(-lg);                 // FMUL + MUFU.EX2
    float r = -__logf(1.0f + e);           // FADD + MUFU.LG2 + FMUL
    return (w * w) * (r * lp) * tscale;
}

__device__ __forceinline__ float quad_term(float4 a, float4 b, float4 c, int idx4) {
    int   t0 = (idx4 << 2) & (T_DIM - 1);
    float tw = (float)(t0 + 1);
    float s  = term_elem(a.x, b.x, c.x, tw);
    s += term_elem(a.y, b.y, c.y, tw + 1.0f);
    s += term_elem(a.z, b.z, c.z, tw + 2.0f);
    s += term_elem(a.w, b.w, c.w, tw + 3.0f);
    return s;
}

// block-reduce + global double atomics + self-resetting finalize
__device__ __forceinline__ void epilogue(float acc_t, float acc_w,
                                         float* __restrict__ out) {
    #pragma unroll
    for (int off = 16; off > 0; off >>= 1) {
        acc_t += __shfl_down_sync(0xffffffffu, acc_t, off);
        acc_w += __shfl_down_sync(0xffffffffu, acc_w, off);
    }

    __shared__ float st[NTHREADS / 32];
    __shared__ float sw[NTHREADS / 32];
    const int lane = threadIdx.x & 31;
    const int wid  = threadIdx.x >> 5;
    if (lane == 0) { st[wid] = acc_t; sw[wid] = acc_w; }
    __syncthreads();

    if (threadIdx.x == 0) {
        float bt = 0.0f, bw = 0.0f;
        #pragma unroll
        for (int k = 0; k < NTHREADS / 32; k++) { bt += st[k]; bw += sw[k]; }

        atomicAdd(&g_acc_t, (double)bt);
        atomicAdd(&g_acc_w, (double)bw);
        __threadfence();
        unsigned int prev = atomicInc(&g_count, gridDim.x - 1);
        if (prev == gridDim.x - 1) {
            double ft = atomicAdd(&g_acc_t, 0.0);
            double fw = atomicAdd(&g_acc_w, 0.0);
            out[0] = (float)(ft / fw);
            atomicExch((unsigned long long*)&g_acc_t, 0ull);
            atomicExch((unsigned long long*)&g_acc_w, 0ull);
        }
    }
}

// hot path: n4 % (2 * gridDim.x * blockDim.x) == 0, no guards
__global__ void __launch_bounds__(NTHREADS)
reinforce_unroll2(const float4* __restrict__ lp,
                  const float4* __restrict__ lg,
                  const float4* __restrict__ w,
                  int n4,
                  float* __restrict__ out)
{
    const int stride = gridDim.x * blockDim.x;
    float acc_t = 0.0f;
    float acc_w = 0.0f;

    for (int i = blockIdx.x * blockDim.x + threadIdx.x; i < n4; i += 2 * stride) {
        const int j = i + stride;
        // 6 independent LDG.128 batched per trip
        float4 a0 = lp[i];
        float4 a1 = lp[j];
        float4 b0 = lg[i];
        float4 b1 = lg[j];
        float4 c0 = w[i];
        float4 c1 = w[j];

        acc_t += quad_term(a0, b0, c0, i);
        acc_t += quad_term(a1, b1, c1, j);
        acc_w += (c0.x + c0.y) + (c0.z + c0.w)
               + (c1.x + c1.y) + (c1.z + c1.w);
    }

    epilogue(acc_t, acc_w, out);
}

// generic fallback (any n4)
__global__ void __launch_bounds__(NTHREADS)
reinforce_generic(const float4* __restrict__ lp,
                  const float4* __restrict__ lg,
                  const float4* __restrict__ w,
                  int n4,
                  float* __restrict__ out)
{
    const int stride = gridDim.x * blockDim.x;
    float acc_t = 0.0f;
    float acc_w = 0.0f;

    for (int i = blockIdx.x * blockDim.x + threadIdx.x; i < n4; i += stride) {
        float4 a = lp[i];
        float4 b = lg[i];
        float4 c = w[i];
        acc_t += quad_term(a, b, c, i);
        acc_w += (c.x + c.y) + (c.z + c.w);
    }

    epilogue(acc_t, acc_w, out);
}

extern "C" void kernel_launch(void* const* d_in, const int* in_sizes, int n_in,
                              void* d_out, int out_size) {
    const float4* lp = (const float4*)d_in[0];
    const float4* lg = (const float4*)d_in[1];
    const float4* w  = (const float4*)d_in[2];
    float* out = (float*)d_out;

    const int n  = in_sizes[0];   // B*T
    const int n4 = n >> 2;

    const int hot_stride = HOTBLOCKS * NTHREADS;           // 2^18
    if (n4 >= 2 * hot_stride && (n4 % (2 * hot_stride)) == 0) {
        reinforce_unroll2<<<HOTBLOCKS, NTHREADS>>>(lp, lg, w, n4, out);
    } else {
        int blocks = GENBLOCKS;
        int max_blocks = (n4 + NTHREADS - 1) / NTHREADS;
        if (blocks > max_blocks) blocks = max_blocks;
        if (blocks < 1) blocks = 1;
        reinforce_generic<<<blocks, NTHREADS>>>(lp, lg, w, n4, out);
    }
}

// round 14
// speedup vs baseline: 1.0173x; 1.0173x over previous
#include <cuda_runtime.h>
#include <math.h>

// result = sum_{b,t} w^2 * log(sigmoid(logit)+EPS) * log_probs * (t+1) / sum(w)
// (reversed cumsum then total sum == (t+1)-weighted sum)
//
// R14 = R9 grid (1184 = 148 SMs x 8 CTAs, perfectly even wave) + R11's
// unroll-2 loop body (6 independent LDG.128 per trip) with a guarded tail so
// no divisibility requirement. Fast MUFU chain, double-atomic epilogue,
// self-resetting counter (graph-replay safe). Handles any n4 in one kernel.

#define T_DIM    16384          // inner dim (power of 2)
#define NTHREADS 256
#define NBLOCKS  (148 * 8)      // exactly 8 CTAs per SM

__device__ double        g_acc_t;   // zero-init at load; reset by last block
__device__ double        g_acc_w;
__device__ unsigned int  g_count;   // wraps to 0 every pass (atomicInc)

__device__ __forceinline__ float term_elem(float lp, float lg, float w, float tscale) {
    // log(sigmoid(lg)+eps) ~= -log1p(exp(-lg)); eps shift < 1e-5 relative here
    float e = __expf(-lg);                 // FMUL + MUFU.EX2
    float r = -__logf(1.0f + e);           // FADD + MUFU.LG2 + FMUL
    return (w * w) * (r * lp) * tscale;
}

__device__ __forceinline__ float quad_term(float4 a, float4 b, float4 c, int idx4) {
    int   t0 = (idx4 << 2) & (T_DIM - 1);
    float tw = (float)(t0 + 1);
    float s  = term_elem(a.x, b.x, c.x, tw);
    s += term_elem(a.y, b.y, c.y, tw + 1.0f);
    s += term_elem(a.z, b.z, c.z, tw + 2.0f);
    s += term_elem(a.w, b.w, c.w, tw + 3.0f);
    return s;
}

__global__ void __launch_bounds__(NTHREADS)
reinforce_kernel(const float4* __restrict__ lp,
                 const float4* __restrict__ lg,
                 const float4* __restrict__ w,
                 int n4,
                 float* __restrict__ out)
{
    const int stride = gridDim.x * blockDim.x;
    float acc_t = 0.0f;
    float acc_w = 0.0f;

    int i = blockIdx.x * blockDim.x + threadIdx.x;

    // unroll-2 main loop: 6 independent LDG.128 batched per trip
    for (; i + stride < n4; i += 2 * stride) {
        const int j = i + stride;
        float4 a0 = lp[i];
        float4 a1 = lp[j];
        float4 b0 = lg[i];
        float4 b1 = lg[j];
        float4 c0 = w[i];
        float4 c1 = w[j];

        acc_t += quad_term(a0, b0, c0, i);
        acc_t += quad_term(a1, b1, c1, j);
        acc_w += (c0.x + c0.y) + (c0.z + c0.w)
               + (c1.x + c1.y) + (c1.z + c1.w);
    }
    // guarded tail (at most one trip)
    if (i < n4) {
        float4 a = lp[i];
        float4 b = lg[i];
        float4 c = w[i];
        acc_t += quad_term(a, b, c, i);
        acc_w += (c.x + c.y) + (c.z + c.w);
    }

    // ---- block reduce (fp32) ----
    #pragma unroll
    for (int off = 16; off > 0; off >>= 1) {
        acc_t += __shfl_down_sync(0xffffffffu, acc_t, off);
        acc_w += __shfl_down_sync(0xffffffffu, acc_w, off);
    }

    __shared__ float st[NTHREADS / 32];
    __shared__ float sw[NTHREADS / 32];
    const int lane = threadIdx.x & 31;
    const int wid  = threadIdx.x >> 5;
    if (lane == 0) { st[wid] = acc_t; sw[wid] = acc_w; }
    __syncthreads();

    if (threadIdx.x == 0) {
        float bt = 0.0f, bw = 0.0f;
        #pragma unroll
        for (int k = 0; k < NTHREADS / 32; k++) { bt += st[k]; bw += sw[k]; }

        atomicAdd(&g_acc_t, (double)bt);
        atomicAdd(&g_acc_w, (double)bw);
        __threadfence();
        // atomicInc with val = gridDim.x-1: last arriver sees gridDim.x-1,
        // counter wraps to 0 for the next graph replay
        unsigned int prev = atomicInc(&g_count, gridDim.x - 1);
        if (prev == gridDim.x - 1) {
            double ft = atomicAdd(&g_acc_t, 0.0);
            double fw = atomicAdd(&g_acc_w, 0.0);
            out[0] = (float)(ft / fw);
            // reset for next replay
            atomicExch((unsigned long long*)&g_acc_t, 0ull);
            atomicExch((unsigned long long*)&g_acc_w, 0ull);
        }
    }
}

extern "C" void kernel_launch(void* const* d_in, const int* in_sizes, int n_in,
                              void* d_out, int out_size) {
    const float4* lp = (const float4*)d_in[0];
    const float4* lg = (const float4*)d_in[1];
    const float4* w  = (const float4*)d_in[2];
    float* out = (float*)d_out;

    const int n  = in_sizes[0];   // B*T
    const int n4 = n >> 2;

    int blocks = NBLOCKS;
    int max_blocks = (n4 + NTHREADS - 1) / NTHREADS;
    if (blocks > max_blocks) blocks = max_blocks;
    if (blocks < 1) blocks = 1;

    reinforce_kernel<<<blocks, NTHREADS>>>(lp, lg, w, n4, out);
}